// round 1
// baseline (speedup 1.0000x reference)
#include <cuda_runtime.h>
#include <cstdint>

#define SH 68           // shared-memory row stride (floats): 16B-aligned rows, conflict-free
#define NHEADS 8
#define NPOW 16
#define NMAX 2048

// ---------------- device scratch (no allocations allowed) ----------------
__device__ float g_powers[NHEADS][NPOW][4096];   // g_powers[h][k] = B_h^k
__device__ float g_sos[4096];                    // prims[16]
__device__ int   g_key[NMAX];                    // c_n (count of 1s) or 100 for sos row
__device__ int   g_len[NMAX];
__device__ unsigned long long g_pack[NMAX];      // 2-bit packed path codes
__device__ int   g_perm[NMAX];                   // n's sorted by key (grouping for writer)

// ---------------- shared 64x64 matmul: row r, 16 cols starting at cb -----
__device__ __forceinline__ void block_mm(const float* __restrict__ A,
                                         const float* __restrict__ B,
                                         float* s, int r, int cb) {
#pragma unroll
    for (int k = 0; k < 16; k++) s[k] = 0.f;
#pragma unroll 4
    for (int j = 0; j < 64; j++) {
        float a = A[r * SH + j];
        const float4 b0 = *(const float4*)(B + j * SH + cb);
        const float4 b1 = *(const float4*)(B + j * SH + cb + 4);
        const float4 b2 = *(const float4*)(B + j * SH + cb + 8);
        const float4 b3 = *(const float4*)(B + j * SH + cb + 12);
        s[0]  += a * b0.x; s[1]  += a * b0.y; s[2]  += a * b0.z; s[3]  += a * b0.w;
        s[4]  += a * b1.x; s[5]  += a * b1.y; s[6]  += a * b1.z; s[7]  += a * b1.w;
        s[8]  += a * b2.x; s[9]  += a * b2.y; s[10] += a * b2.z; s[11] += a * b2.w;
        s[12] += a * b3.x; s[13] += a * b3.y; s[14] += a * b3.z; s[15] += a * b3.w;
    }
}

// ---------------- expm via Paterson-Stockmeyer degree-12 Taylor ----------
// Only matrices 8..16 are ever used by the reference's math.
// exp(H) = B0 + A4*(B1 + A4*(B2 + A4/12!)), A4 = H^4, Bi = combos of I,H,H2,H3.
// 5 matmuls total. ||H||<=1 -> truncation < 1/13! ~ 1.6e-10.
__global__ void expm_kernel(const float* __restrict__ raw) {
    extern __shared__ float sm[];
    float* H  = sm;
    float* P2 = sm + 1 * 64 * SH;
    float* P3 = sm + 2 * 64 * SH;
    float* P4 = sm + 3 * 64 * SH;
    float* R  = sm + 4 * 64 * SH;
    int bx = blockIdx.x;                 // 0..8 -> matrix 8+bx
    const float* A = raw + (size_t)(8 + bx) * 4096;
    int tid = threadIdx.x;
    int r  = tid >> 2;
    int cb = (tid & 3) << 4;

    // H = (A - A^T)/64, padded layout
    for (int i = tid; i < 4096; i += 256) {
        int rr = i >> 6, cc = i & 63;
        H[rr * SH + cc] = (A[rr * 64 + cc] - A[cc * 64 + rr]) * (1.0f / 64.0f);
    }
    __syncthreads();

    float s[16];
    // P2 = H*H
    block_mm(H, H, s, r, cb);
#pragma unroll
    for (int k = 0; k < 16; k++) P2[r * SH + cb + k] = s[k];
    __syncthreads();
    // P3 = P2*H
    block_mm(P2, H, s, r, cb);
#pragma unroll
    for (int k = 0; k < 16; k++) P3[r * SH + cb + k] = s[k];
    __syncthreads();
    // P4 = P2*P2
    block_mm(P2, P2, s, r, cb);
#pragma unroll
    for (int k = 0; k < 16; k++) P4[r * SH + cb + k] = s[k];
    __syncthreads();
    // R = B2 + P4/12!  (B2 = I/8! + H/9! + H2/10! + H3/11!)
#pragma unroll
    for (int k = 0; k < 16; k++) {
        int c = cb + k; float d = (r == c) ? 1.f : 0.f;
        R[r * SH + c] = 2.48015873e-5f * d
                      + 2.75573192e-6f * H[r * SH + c]
                      + 2.75573192e-7f * P2[r * SH + c]
                      + 2.50521084e-8f * P3[r * SH + c]
                      + 2.08767570e-9f * P4[r * SH + c];
    }
    __syncthreads();
    // R = B1 + P4*R  (B1 = I/24 + H/120 + H2/720 + H3/5040)
    block_mm(P4, R, s, r, cb);
    __syncthreads();
#pragma unroll
    for (int k = 0; k < 16; k++) {
        int c = cb + k; float d = (r == c) ? 1.f : 0.f;
        R[r * SH + c] = s[k] + (1.f / 24.f) * d
                      + (1.f / 120.f) * H[r * SH + c]
                      + (1.f / 720.f) * P2[r * SH + c]
                      + (1.f / 5040.f) * P3[r * SH + c];
    }
    __syncthreads();
    // result = B0 + P4*R  (B0 = I + H + H2/2 + H3/6)
    block_mm(P4, R, s, r, cb);
#pragma unroll
    for (int k = 0; k < 16; k++) {
        int c = cb + k; float d = (r == c) ? 1.f : 0.f;
        float v = s[k] + d + H[r * SH + c]
                + 0.5f * P2[r * SH + c] + (1.f / 6.f) * P3[r * SH + c];
        if (bx == 8) {
            g_sos[r * 64 + c] = v;
        } else {
            g_powers[bx][1][r * 64 + c] = v;   // B_h^1
            g_powers[bx][0][r * 64 + c] = d;   // B_h^0 = I
        }
    }
}

// ---------------- log-depth power ladder: g_powers[h][d] = [a]*[b] -------
struct MulList { int a[4]; int b[4]; int d[4]; };

__global__ void powmul_kernel(MulList ml) {
    __shared__ float As[64 * SH], Bs[64 * SH];
    int h = blockIdx.y, i = blockIdx.x;
    const float* A = g_powers[h][ml.a[i]];
    const float* B = g_powers[h][ml.b[i]];
    int tid = threadIdx.x, r = tid >> 2, cb = (tid & 3) << 4;
    for (int idx = tid; idx < 4096; idx += 256) {
        int rr = idx >> 6, cc = idx & 63;
        As[rr * SH + cc] = A[idx];
        Bs[rr * SH + cc] = B[idx];
    }
    __syncthreads();
    float s[16];
    block_mm(As, Bs, s, r, cb);
    float* D = g_powers[h][ml.d[i]];
#pragma unroll
    for (int k = 0; k < 16; k++) D[r * 64 + cb + k] = s[k];
}

// ---------------- path stats + grouping (sorted-by-key perm) -------------
__global__ void group_kernel(const int* __restrict__ pw, int L, int N) {
    __shared__ int cnt[20], off[20];
    int tid = threadIdx.x;
    if (tid < 20) cnt[tid] = 0;
    __syncthreads();
    for (int n = tid; n < N; n += blockDim.x) {
        const int* p = pw + (size_t)n * L;
        int c = 0, len = 0;
        unsigned long long pack = 0ull;
        for (int t = 0; t < L; t++) {
            int w = p[t];
            int code = (w == -1) ? 0 : w;          // values -1,1,2,3(PAD) -> 0,1,2,3
            pack |= ((unsigned long long)(code & 3)) << (2 * t);
            if (w != 3) len++;                     // PAD = BF+1 = 3
            if (w == 1) c++;                       // only idx==1 hits the gate
        }
        int key = (p[0] == -1) ? 100 : c;          // sos row sentinel
        g_key[n] = key; g_len[n] = len; g_pack[n] = pack;
        int bin = (key == 100) ? 16 : key;
        atomicAdd(&cnt[bin], 1);
    }
    __syncthreads();
    if (tid == 0) { int s0 = 0; for (int b = 0; b < 20; b++) { off[b] = s0; s0 += cnt[b]; } }
    __syncthreads();
    for (int n = tid; n < N; n += blockDim.x) {
        int key = g_key[n];
        int bin = (key == 100) ? 16 : key;
        int pos = atomicAdd(&off[bin], 1);
        g_perm[pos] = n;
    }
}

// ---------------- maps writer: broadcast power tiles -> 256 MB out -------
// Each block holds one 16 KB source tile in registers and writes 8 destination
// tiles; perm is key-sorted so the cached tile almost never reloads.
__global__ void maps_writer(float4* __restrict__ out) {
    int h = blockIdx.y;
    int base = blockIdx.x << 3;
    int t = threadIdx.x;
    float4 v0, v1, v2, v3;
    int cached = -12345;
#pragma unroll 1
    for (int e = 0; e < 8; e++) {
        int n = g_perm[base + e];
        int key = g_key[n];
        if (key != cached) {
            const float4* src = (key == 100) ? (const float4*)g_sos
                                             : (const float4*)g_powers[h][key];
            v0 = src[t]; v1 = src[t + 256]; v2 = src[t + 512]; v3 = src[t + 768];
            cached = key;
        }
        float4* dst = out + ((size_t)((unsigned)(n * NHEADS + h)) << 10);
        __stcs(dst + t,        v0);
        __stcs(dst + t + 256,  v1);
        __stcs(dst + t + 512,  v2);
        __stcs(dst + t + 768,  v3);
    }
}

// ---------------- steps: packed-prefix compare, 16 MB out ----------------
__global__ void steps_kernel(float* __restrict__ out, int N) {
    int i = blockIdx.y;
    int j = (blockIdx.x << 8) + threadIdx.x;
    unsigned long long pi = g_pack[i], pj = g_pack[j];
    int li = g_len[i], lj = g_len[j];
    unsigned long long d = pi ^ pj;
    int pos = d ? ((__ffsll((long long)d) - 1) >> 1) : 64;
    int mn = min(li, lj), mx = max(li, lj);
    int common = min(pos, mn);
    __stcs(out + (size_t)i * N + j, (float)(mx - common));
}

// ---------------- launch --------------------------------------------------
extern "C" void kernel_launch(void* const* d_in, const int* in_sizes, int n_in,
                              void* d_out, int out_size) {
    const float* raw = (const float*)d_in[0];
    const int*   pw  = (const int*)d_in[1];
    const int N = 2048;
    const int L = in_sizes[1] / N;
    float* out = (float*)d_out;

    size_t expm_smem = 5ull * 64 * SH * sizeof(float);   // ~87 KB
    cudaFuncSetAttribute(expm_kernel, cudaFuncAttributeMaxDynamicSharedMemorySize,
                         (int)expm_smem);

    group_kernel<<<1, 1024>>>(pw, L, N);
    expm_kernel<<<9, 256, expm_smem>>>(raw);

    { MulList m = {{1}, {1}, {2}};                          powmul_kernel<<<dim3(1, NHEADS), 256>>>(m); }
    { MulList m = {{2, 2}, {1, 2}, {3, 4}};                 powmul_kernel<<<dim3(2, NHEADS), 256>>>(m); }
    { MulList m = {{4, 4, 4, 4}, {1, 2, 3, 4}, {5, 6, 7, 8}}; powmul_kernel<<<dim3(4, NHEADS), 256>>>(m); }
    { MulList m = {{8, 8}, {1, 2}, {9, 10}};                powmul_kernel<<<dim3(2, NHEADS), 256>>>(m); }

    maps_writer<<<dim3(N / 8, NHEADS), 256>>>((float4*)out);

    size_t maps_elems = (size_t)N * NHEADS * 64 * 64;
    if ((size_t)out_size >= maps_elems + (size_t)N * N)
        steps_kernel<<<dim3(N / 256, N), 256>>>(out + maps_elems, N);
}

// round 2
// speedup vs baseline: 2.2831x; 2.2831x over previous
#include <cuda_runtime.h>
#include <cstdint>

#define SH 68                    // smem row stride in floats (16B-aligned rows)
#define SZ (64 * SH)             // one 64x64 padded matrix in floats
#define NHEADS 8
#define NPOW 16
#define NMAX 2048

// ---------------- device scratch ----------------
__device__ float g_powers[NHEADS][NPOW][4096];   // g_powers[h][k] = B_h^k
__device__ float g_sos[4096];
__device__ int   g_key[NMAX];
__device__ int   g_len[NMAX];
__device__ unsigned long long g_pack[NMAX];
__device__ int   g_perm[NMAX];

// packed f32x2 FFMA: acc(pair) += (a,a) * bp(pair)
#define FFMA2(acc, a, bp)                                                     \
    asm("{\n\t.reg .b64 t;\n\tmov.b64 t, {%1,%1};\n\t"                        \
        "fma.rn.f32x2 %0, t, %2, %0;\n\t}"                                    \
        : "+l"(acc) : "f"(a), "l"(bp))

__device__ __forceinline__ float f2lo(unsigned long long v) {
    return __uint_as_float((unsigned)(v & 0xffffffffull));
}
__device__ __forceinline__ float f2hi(unsigned long long v) {
    return __uint_as_float((unsigned)(v >> 32));
}

// ---- 64x64 matmul: C = A*B given AT (A transposed) and B in smem ----
// warp w: rows 8w..8w+7; lane l: columns 2l, 2l+1 (packed pair).
// Optionally also writes CT (C transposed). Caller handles __syncthreads.
__device__ __forceinline__ void mm64(const float* __restrict__ AT,
                                     const float* __restrict__ B,
                                     float* __restrict__ C,
                                     float* __restrict__ CT) {
    int tid = threadIdx.x;
    int w = tid >> 5, l = tid & 31;
    const float* at = AT + (w << 3);
    const float* bb = B + (l << 1);
    unsigned long long a0 = 0, a1 = 0, a2 = 0, a3 = 0, a4 = 0, a5 = 0, a6 = 0, a7 = 0;
#pragma unroll 4
    for (int j = 0; j < 64; j++) {
        float4 x = *(const float4*)(at + j * SH);        // broadcast across warp
        float4 y = *(const float4*)(at + j * SH + 4);    // broadcast
        unsigned long long bp = *(const unsigned long long*)(bb + j * SH);
        FFMA2(a0, x.x, bp); FFMA2(a1, x.y, bp); FFMA2(a2, x.z, bp); FFMA2(a3, x.w, bp);
        FFMA2(a4, y.x, bp); FFMA2(a5, y.y, bp); FFMA2(a6, y.z, bp); FFMA2(a7, y.w, bp);
    }
    float* cp = C + (w << 3) * SH + (l << 1);
    *(unsigned long long*)(cp + 0 * SH) = a0;
    *(unsigned long long*)(cp + 1 * SH) = a1;
    *(unsigned long long*)(cp + 2 * SH) = a2;
    *(unsigned long long*)(cp + 3 * SH) = a3;
    *(unsigned long long*)(cp + 4 * SH) = a4;
    *(unsigned long long*)(cp + 5 * SH) = a5;
    *(unsigned long long*)(cp + 6 * SH) = a6;
    *(unsigned long long*)(cp + 7 * SH) = a7;
    if (CT) {
        float* t0 = CT + (l << 1) * SH + (w << 3);
        float* t1 = t0 + SH;
        *(float4*)(t0)     = make_float4(f2lo(a0), f2lo(a1), f2lo(a2), f2lo(a3));
        *(float4*)(t0 + 4) = make_float4(f2lo(a4), f2lo(a5), f2lo(a6), f2lo(a7));
        *(float4*)(t1)     = make_float4(f2hi(a0), f2hi(a1), f2hi(a2), f2hi(a3));
        *(float4*)(t1 + 4) = make_float4(f2hi(a4), f2hi(a5), f2hi(a6), f2hi(a7));
    }
}

// power-chain op table: slots 0:X 1:XT 2:Y 3:YT 4:Z 5:ZT 6:W ; {aT, b, d, dT}
struct Op { signed char aT, b, d, dT; };
__device__ __constant__ Op c_chain[9][4] = {
    /*k=2*/ {{1,0,2,-1},{-1,0,0,0},{-1,0,0,0},{-1,0,0,0}},
    /*k=3*/ {{1,0,2,-1},{1,2,4,-1},{-1,0,0,0},{-1,0,0,0}},
    /*k=4*/ {{1,0,2, 3},{3,2,4,-1},{-1,0,0,0},{-1,0,0,0}},
    /*k=5*/ {{1,0,2, 3},{3,2,4,-1},{1,4,6,-1},{-1,0,0,0}},
    /*k=6*/ {{1,0,2, 3},{3,2,4,-1},{3,4,6,-1},{-1,0,0,0}},
    /*k=7*/ {{1,0,2, 3},{3,2,4,-1},{3,4,6,-1},{1,6,4,-1}},
    /*k=8*/ {{1,0,2, 3},{3,2,4, 5},{5,4,6,-1},{-1,0,0,0}},
    /*k=9*/ {{1,0,2, 3},{3,2,4, 5},{5,4,6,-1},{1,6,4,-1}},
    /*k=10*/{{1,0,2, 3},{3,2,4, 5},{5,4,6,-1},{3,6,4,-1}},
};

// ---------------- fused prepare: expm + power ladder + grouping ----------
// blocks 0..71: (h = b/9, k = b%9 + 2) -> expm then B_h^k
// block 72: expm(sos); block 73: path grouping
__global__ void __launch_bounds__(256, 1)
prepare_kernel(const float* __restrict__ raw, const int* __restrict__ pw,
               int L, int N) {
    extern __shared__ float sm[];
    int b = blockIdx.x;
    int tid = threadIdx.x;

    if (b == 73) {   // ---- grouping ----
        int* cnt = (int*)sm;
        int* off = cnt + 32;
        if (tid < 20) cnt[tid] = 0;
        __syncthreads();
        for (int n = tid; n < N; n += 256) {
            const int* p = pw + (size_t)n * L;
            int c = 0, len = 0;
            unsigned long long pack = 0ull;
            for (int t = 0; t < L; t++) {
                int wv = p[t];
                int code = (wv == -1) ? 0 : wv;
                pack |= ((unsigned long long)(code & 3)) << (2 * t);
                if (wv != 3) len++;          // PAD = 3
                if (wv == 1) c++;            // only step==1 hits the gate
            }
            int key = (p[0] == -1) ? 100 : c;
            g_key[n] = key; g_len[n] = len; g_pack[n] = pack;
            atomicAdd(&cnt[(key == 100) ? 16 : key], 1);
        }
        __syncthreads();
        if (tid == 0) { int s0 = 0; for (int q = 0; q < 20; q++) { off[q] = s0; s0 += cnt[q]; } }
        __syncthreads();
        for (int n = tid; n < N; n += 256) {
            int key = g_key[n];
            int pos = atomicAdd(&off[(key == 100) ? 16 : key], 1);
            g_perm[pos] = n;
        }
        return;
    }

    int h = (b < 72) ? (b / 9) : 8;          // 8 -> sos matrix (prims[16])
    int k = (b < 72) ? (b % 9) + 2 : 0;
    const float* A = raw + (size_t)(8 + h) * 4096;

    float* H   = sm + 0 * SZ;   // later reused as X (=E)
    float* HT  = sm + 1 * SZ;   // later XT
    float* P2  = sm + 2 * SZ;
    float* P3  = sm + 3 * SZ;
    float* P3T = sm + 4 * SZ;
    float* Q   = sm + 5 * SZ;
    float* M   = sm + 6 * SZ;

    int w = tid >> 5, l = tid & 31;
    int r0 = w << 3, c0 = l << 1;

    // H = (A - A^T)/64, both forms
    for (int i = tid; i < 4096; i += 256) {
        int rr = i >> 6, cc = i & 63;
        float v = (A[rr * 64 + cc] - A[cc * 64 + rr]) * (1.0f / 64.0f);
        H[rr * SH + cc] = v;
        HT[cc * SH + rr] = v;
    }
    __syncthreads();

    // ---- expm, degree-9 Paterson-Stockmeyer: 4 matmuls ----
    mm64(HT, H, P2, nullptr);                 // P2 = H^2
    __syncthreads();
    mm64(HT, P2, P3, P3T);                    // P3 = H^3
    __syncthreads();
    // Q = I/720 + H/5040 + P2/40320 + P3/362880
#pragma unroll
    for (int i = 0; i < 8; i++) {
        int r = r0 + i;
#pragma unroll
        for (int cc = 0; cc < 2; cc++) {
            int c = c0 + cc;
            float d = (r == c) ? 1.f : 0.f;
            Q[r * SH + c] = 1.38888889e-3f * d
                          + 1.98412698e-4f * H[r * SH + c]
                          + 2.48015873e-5f * P2[r * SH + c]
                          + 2.75573192e-6f * P3[r * SH + c];
        }
    }
    __syncthreads();
    mm64(P3T, Q, M, nullptr);                 // M = P3*Q2
    __syncthreads();
    // M += I/6 + H/24 + P2/120
#pragma unroll
    for (int i = 0; i < 8; i++) {
        int r = r0 + i;
#pragma unroll
        for (int cc = 0; cc < 2; cc++) {
            int c = c0 + cc;
            float d = (r == c) ? 1.f : 0.f;
            M[r * SH + c] += (1.f / 6.f) * d
                           + (1.f / 24.f) * H[r * SH + c]
                           + (1.f / 120.f) * P2[r * SH + c];
        }
    }
    __syncthreads();
    mm64(P3T, M, Q, nullptr);                 // Q = P3*(Q1 + M1)
    __syncthreads();
    // E = Q + I + H + 0.5*P2 -> write into H/HT slots (elementwise, own cells)
#pragma unroll
    for (int i = 0; i < 8; i++) {
        int r = r0 + i;
#pragma unroll
        for (int cc = 0; cc < 2; cc++) {
            int c = c0 + cc;
            float d = (r == c) ? 1.f : 0.f;
            float e = Q[r * SH + c] + d + H[r * SH + c] + 0.5f * P2[r * SH + c];
            H[r * SH + c] = e;
            HT[c * SH + r] = e;
        }
    }
    __syncthreads();

    if (b == 72) {   // sos: store expm and exit
#pragma unroll
        for (int i = 0; i < 8; i++) {
            int r = r0 + i;
            g_sos[r * 64 + c0]     = H[r * SH + c0];
            g_sos[r * 64 + c0 + 1] = H[r * SH + c0 + 1];
        }
        return;
    }

    if (k == 2) {   // this block also publishes p0 = I and p1 = E
#pragma unroll
        for (int i = 0; i < 8; i++) {
            int r = r0 + i;
            g_powers[h][0][r * 64 + c0]     = (r == c0) ? 1.f : 0.f;
            g_powers[h][0][r * 64 + c0 + 1] = (r == c0 + 1) ? 1.f : 0.f;
            g_powers[h][1][r * 64 + c0]     = H[r * SH + c0];
            g_powers[h][1][r * 64 + c0 + 1] = H[r * SH + c0 + 1];
        }
    }

    // ---- square-and-multiply chain to X^k ----
    int outslot = 0;
#pragma unroll 1
    for (int s = 0; s < 4; s++) {
        Op op = c_chain[k - 2][s];
        if (op.aT < 0) break;
        mm64(sm + op.aT * SZ, sm + op.b * SZ, sm + op.d * SZ,
             (op.dT >= 0) ? (sm + op.dT * SZ) : nullptr);
        outslot = op.d;
        __syncthreads();
    }
    const float* OUT = sm + outslot * SZ;
#pragma unroll
    for (int i = 0; i < 8; i++) {
        int r = r0 + i;
        *(unsigned long long*)&g_powers[h][k][r * 64 + c0] =
            *(const unsigned long long*)&OUT[r * SH + c0];
    }
}

// ---------------- maps writer: 256 MB gather-broadcast ----------------
__global__ void maps_writer(float4* __restrict__ out) {
    int h = blockIdx.y;
    int base = blockIdx.x << 3;
    int t = threadIdx.x;
    float4 v0, v1, v2, v3;
    int cached = -12345;
#pragma unroll 1
    for (int e = 0; e < 8; e++) {
        int n = g_perm[base + e];
        int key = g_key[n];
        if (key != cached) {
            const float4* src = (key == 100) ? (const float4*)g_sos
                                             : (const float4*)g_powers[h][key];
            v0 = src[t]; v1 = src[t + 256]; v2 = src[t + 512]; v3 = src[t + 768];
            cached = key;
        }
        float4* dst = out + ((size_t)((unsigned)(n * NHEADS + h)) << 10);
        __stcs(dst + t,       v0);
        __stcs(dst + t + 256, v1);
        __stcs(dst + t + 512, v2);
        __stcs(dst + t + 768, v3);
    }
}

// ---------------- steps ----------------
__global__ void steps_kernel(float* __restrict__ out, int N) {
    int i = blockIdx.y;
    int j = (blockIdx.x << 8) + threadIdx.x;
    unsigned long long pi = g_pack[i], pj = g_pack[j];
    int li = g_len[i], lj = g_len[j];
    unsigned long long d = pi ^ pj;
    int pos = d ? ((__ffsll((long long)d) - 1) >> 1) : 64;
    int mn = min(li, lj), mx = max(li, lj);
    int common = min(pos, mn);
    __stcs(out + (size_t)i * N + j, (float)(mx - common));
}

// ---------------- launch ----------------
extern "C" void kernel_launch(void* const* d_in, const int* in_sizes, int n_in,
                              void* d_out, int out_size) {
    const float* raw = (const float*)d_in[0];
    const int*   pw  = (const int*)d_in[1];
    const int N = 2048;
    const int L = in_sizes[1] / N;
    float* out = (float*)d_out;

    size_t smem = 7ull * SZ * sizeof(float);   // ~119 KB
    cudaFuncSetAttribute(prepare_kernel, cudaFuncAttributeMaxDynamicSharedMemorySize,
                         (int)smem);

    prepare_kernel<<<74, 256, smem>>>(raw, pw, L, N);

    size_t maps_elems = (size_t)N * NHEADS * 64 * 64;
    if ((size_t)out_size >= maps_elems + (size_t)N * N)
        steps_kernel<<<dim3(N / 256, N), 256>>>(out + maps_elems, N);

    maps_writer<<<dim3(N / 8, NHEADS), 256>>>((float4*)out);
}

// round 3
// speedup vs baseline: 2.2937x; 1.0046x over previous
#include <cuda_runtime.h>
#include <cstdint>

#define SH 68                    // smem row stride in floats (16B-aligned rows)
#define SZ (64 * SH)             // one 64x64 padded matrix in floats
#define NHEADS 8
#define NPOW 16
#define NMAX 2048
#define PT 512                   // prepare threads

// ---------------- device scratch ----------------
__device__ float g_powers[NHEADS][NPOW][4096];   // g_powers[h][k] = B_h^k
__device__ float g_sos[4096];
__device__ int   g_key[NMAX];
__device__ int   g_len[NMAX];
__device__ unsigned long long g_pack[NMAX];
__device__ int   g_perm[NMAX];

// packed f32x2 FFMA: acc(pair) += (a,a) * bp(pair)
#define FFMA2(acc, a, bp)                                                     \
    asm("{\n\t.reg .b64 t;\n\tmov.b64 t, {%1,%1};\n\t"                        \
        "fma.rn.f32x2 %0, t, %2, %0;\n\t}"                                    \
        : "+l"(acc) : "f"(a), "l"(bp))

__device__ __forceinline__ float f2lo(unsigned long long v) {
    return __uint_as_float((unsigned)(v & 0xffffffffull));
}
__device__ __forceinline__ float f2hi(unsigned long long v) {
    return __uint_as_float((unsigned)(v >> 32));
}

// ---- 64x64 matmul with 512 threads: C = A*B given AT and B in smem ----
// warp w (16): rows 4w..4w+3; lane l: cols 2l, 2l+1 (packed f32x2 pair).
// Per j-iter: 1 broadcast LDS.128 (A col chunk) + 1 LDS.64 (B pair) + 4 FFMA2.
__device__ __forceinline__ void mm64(const float* __restrict__ AT,
                                     const float* __restrict__ B,
                                     float* __restrict__ C,
                                     float* __restrict__ CT) {
    int tid = threadIdx.x;
    int w = tid >> 5, l = tid & 31;
    const float* at = AT + (w << 2);
    const float* bb = B + (l << 1);
    unsigned long long a0 = 0, a1 = 0, a2 = 0, a3 = 0;
#pragma unroll 8
    for (int j = 0; j < 64; j++) {
        float4 x = *(const float4*)(at + j * SH);                  // broadcast
        unsigned long long bp = *(const unsigned long long*)(bb + j * SH);
        FFMA2(a0, x.x, bp); FFMA2(a1, x.y, bp);
        FFMA2(a2, x.z, bp); FFMA2(a3, x.w, bp);
    }
    float* cp = C + (w << 2) * SH + (l << 1);
    *(unsigned long long*)(cp + 0 * SH) = a0;
    *(unsigned long long*)(cp + 1 * SH) = a1;
    *(unsigned long long*)(cp + 2 * SH) = a2;
    *(unsigned long long*)(cp + 3 * SH) = a3;
    if (CT) {
        float* t0 = CT + (l << 1) * SH + (w << 2);
        float* t1 = t0 + SH;
        *(float4*)(t0) = make_float4(f2lo(a0), f2lo(a1), f2lo(a2), f2lo(a3));
        *(float4*)(t1) = make_float4(f2hi(a0), f2hi(a1), f2hi(a2), f2hi(a3));
    }
}

// power-chain op table: slots 0:X 1:XT 2:Y 3:YT 4:Z 5:ZT 6:W ; {aT, b, d, dT}
struct Op { signed char aT, b, d, dT; };
__device__ __constant__ Op c_chain[9][4] = {
    /*k=2*/ {{1,0,2,-1},{-1,0,0,0},{-1,0,0,0},{-1,0,0,0}},
    /*k=3*/ {{1,0,2,-1},{1,2,4,-1},{-1,0,0,0},{-1,0,0,0}},
    /*k=4*/ {{1,0,2, 3},{3,2,4,-1},{-1,0,0,0},{-1,0,0,0}},
    /*k=5*/ {{1,0,2, 3},{3,2,4,-1},{1,4,6,-1},{-1,0,0,0}},
    /*k=6*/ {{1,0,2, 3},{3,2,4,-1},{3,4,6,-1},{-1,0,0,0}},
    /*k=7*/ {{1,0,2, 3},{3,2,4,-1},{3,4,6,-1},{1,6,4,-1}},
    /*k=8*/ {{1,0,2, 3},{3,2,4, 5},{5,4,6,-1},{-1,0,0,0}},
    /*k=9*/ {{1,0,2, 3},{3,2,4, 5},{5,4,6,-1},{1,6,4,-1}},
    /*k=10*/{{1,0,2, 3},{3,2,4, 5},{5,4,6,-1},{3,6,4,-1}},
};

// ---------------- fused prepare: expm + power ladder + grouping ----------
// blocks 0..71: (h = b/9, k = b%9 + 2) -> expm then B_h^k
// block 72: expm(sos); block 73: path grouping
__global__ void __launch_bounds__(PT, 1)
prepare_kernel(const float* __restrict__ raw, const int* __restrict__ pw,
               int L, int N) {
    extern __shared__ float sm[];
    int b = blockIdx.x;
    int tid = threadIdx.x;

    if (b == 73) {   // ---- grouping ----
        int* cnt = (int*)sm;
        int* off = cnt + 32;
        if (tid < 20) cnt[tid] = 0;
        __syncthreads();
        for (int n = tid; n < N; n += PT) {
            const int* p = pw + (size_t)n * L;
            int c = 0, len = 0;
            unsigned long long pack = 0ull;
            for (int t = 0; t < L; t++) {
                int wv = p[t];
                int code = (wv == -1) ? 0 : wv;
                pack |= ((unsigned long long)(code & 3)) << (2 * t);
                if (wv != 3) len++;          // PAD = 3
                if (wv == 1) c++;            // only step==1 hits the gate
            }
            int key = (p[0] == -1) ? 100 : c;
            g_key[n] = key; g_len[n] = len; g_pack[n] = pack;
            atomicAdd(&cnt[(key == 100) ? 16 : key], 1);
        }
        __syncthreads();
        if (tid == 0) { int s0 = 0; for (int q = 0; q < 20; q++) { off[q] = s0; s0 += cnt[q]; } }
        __syncthreads();
        for (int n = tid; n < N; n += PT) {
            int key = g_key[n];
            int pos = atomicAdd(&off[(key == 100) ? 16 : key], 1);
            g_perm[pos] = n;
        }
        return;
    }

    int h = (b < 72) ? (b / 9) : 8;          // 8 -> sos matrix (prims[16])
    int k = (b < 72) ? (b % 9) + 2 : 0;
    const float* A = raw + (size_t)(8 + h) * 4096;

    float* X   = sm + 0 * SZ;   // H, later E
    float* XT  = sm + 1 * SZ;
    float* P2  = sm + 2 * SZ;
    float* P3  = sm + 3 * SZ;
    float* P3T = sm + 4 * SZ;
    float* Q   = sm + 5 * SZ;
    float* F   = sm + 6 * SZ;

    int w = tid >> 5, l = tid & 31;
    int r0 = w << 2, c0 = l << 1;

    // H = (A - A^T)/64, both forms
    for (int i = tid; i < 4096; i += PT) {
        int rr = i >> 6, cc = i & 63;
        float v = (A[rr * 64 + cc] - A[cc * 64 + rr]) * (1.0f / 64.0f);
        X[rr * SH + cc] = v;
        XT[cc * SH + rr] = v;
    }
    __syncthreads();

    // ---- expm, degree-6 Paterson-Stockmeyer: 3 matmuls ----
    mm64(XT, X, P2, nullptr);                 // P2 = H^2
    __syncthreads();
    mm64(XT, P2, P3, P3T);                    // P3 = H^3 (+ transpose)
    __syncthreads();
    // Q = H/24 + P2/120 + P3/720
#pragma unroll
    for (int i = 0; i < 4; i++) {
        int r = r0 + i;
#pragma unroll
        for (int cc = 0; cc < 2; cc++) {
            int c = c0 + cc;
            Q[r * SH + c] = (1.f / 24.f)  * X[r * SH + c]
                          + (1.f / 120.f) * P2[r * SH + c]
                          + (1.f / 720.f) * P3[r * SH + c];
        }
    }
    __syncthreads();
    mm64(P3T, Q, F, nullptr);                 // F = P3*Q
    __syncthreads();
    // E = F + I + H + P2/2 + P3/6 -> write into X/XT (own cells only)
#pragma unroll
    for (int i = 0; i < 4; i++) {
        int r = r0 + i;
#pragma unroll
        for (int cc = 0; cc < 2; cc++) {
            int c = c0 + cc;
            float d = (r == c) ? 1.f : 0.f;
            float e = F[r * SH + c] + d + X[r * SH + c]
                    + 0.5f * P2[r * SH + c] + (1.f / 6.f) * P3[r * SH + c];
            X[r * SH + c] = e;
            XT[c * SH + r] = e;
        }
    }
    __syncthreads();

    if (b == 72) {   // sos: store expm and exit
#pragma unroll
        for (int i = 0; i < 4; i++) {
            int r = r0 + i;
            *(unsigned long long*)&g_sos[r * 64 + c0] =
                *(const unsigned long long*)&X[r * SH + c0];
        }
        return;
    }

    if (k == 2) {   // this block also publishes p0 = I and p1 = E
#pragma unroll
        for (int i = 0; i < 4; i++) {
            int r = r0 + i;
            g_powers[h][0][r * 64 + c0]     = (r == c0) ? 1.f : 0.f;
            g_powers[h][0][r * 64 + c0 + 1] = (r == c0 + 1) ? 1.f : 0.f;
            *(unsigned long long*)&g_powers[h][1][r * 64 + c0] =
                *(const unsigned long long*)&X[r * SH + c0];
        }
    }

    // ---- square-and-multiply chain to X^k ----
    int outslot = 0;
#pragma unroll 1
    for (int s = 0; s < 4; s++) {
        Op op = c_chain[k - 2][s];
        if (op.aT < 0) break;
        mm64(sm + op.aT * SZ, sm + op.b * SZ, sm + op.d * SZ,
             (op.dT >= 0) ? (sm + op.dT * SZ) : nullptr);
        outslot = op.d;
        __syncthreads();
    }
    const float* OUT = sm + outslot * SZ;
#pragma unroll
    for (int i = 0; i < 4; i++) {
        int r = r0 + i;
        *(unsigned long long*)&g_powers[h][k][r * 64 + c0] =
            *(const unsigned long long*)&OUT[r * SH + c0];
    }
}

// ---------------- maps writer: 256 MB gather-broadcast ----------------
__global__ void maps_writer(float4* __restrict__ out) {
    int h = blockIdx.y;
    int base = blockIdx.x << 3;
    int t = threadIdx.x;
    float4 v0, v1, v2, v3;
    int cached = -12345;
#pragma unroll 1
    for (int e = 0; e < 8; e++) {
        int n = g_perm[base + e];
        int key = g_key[n];
        if (key != cached) {
            const float4* src = (key == 100) ? (const float4*)g_sos
                                             : (const float4*)g_powers[h][key];
            v0 = src[t]; v1 = src[t + 256]; v2 = src[t + 512]; v3 = src[t + 768];
            cached = key;
        }
        float4* dst = out + ((size_t)((unsigned)(n * NHEADS + h)) << 10);
        __stcs(dst + t,       v0);
        __stcs(dst + t + 256, v1);
        __stcs(dst + t + 512, v2);
        __stcs(dst + t + 768, v3);
    }
}

// ---------------- steps ----------------
__global__ void steps_kernel(float* __restrict__ out, int N) {
    int i = blockIdx.y;
    int j = (blockIdx.x << 8) + threadIdx.x;
    unsigned long long pi = g_pack[i], pj = g_pack[j];
    int li = g_len[i], lj = g_len[j];
    unsigned long long d = pi ^ pj;
    int pos = d ? ((__ffsll((long long)d) - 1) >> 1) : 64;
    int mn = min(li, lj), mx = max(li, lj);
    int common = min(pos, mn);
    __stcs(out + (size_t)i * N + j, (float)(mx - common));
}

// ---------------- launch ----------------
extern "C" void kernel_launch(void* const* d_in, const int* in_sizes, int n_in,
                              void* d_out, int out_size) {
    const float* raw = (const float*)d_in[0];
    const int*   pw  = (const int*)d_in[1];
    const int N = 2048;
    const int L = in_sizes[1] / N;
    float* out = (float*)d_out;

    size_t smem = 7ull * SZ * sizeof(float);   // ~119 KB
    cudaFuncSetAttribute(prepare_kernel, cudaFuncAttributeMaxDynamicSharedMemorySize,
                         (int)smem);

    prepare_kernel<<<74, PT, smem>>>(raw, pw, L, N);

    size_t maps_elems = (size_t)N * NHEADS * 64 * 64;
    if ((size_t)out_size >= maps_elems + (size_t)N * N)
        steps_kernel<<<dim3(N / 256, N), 256>>>(out + maps_elems, N);

    maps_writer<<<dim3(N / 8, NHEADS), 256>>>((float4*)out);
}

// round 4
// speedup vs baseline: 2.6282x; 1.1458x over previous
#include <cuda_runtime.h>
#include <cstdint>

#define SH 68                    // smem row stride in floats
#define SZ (64 * SH)
#define NHEADS 8
#define NPOW 16
#define NMAX 2048

// ---------------- device scratch ----------------
__device__ float g_powers[NHEADS][NPOW][4096];   // g_powers[h][k] = B_h^k
__device__ float g_sos[4096];
__device__ int   g_key[NMAX];
__device__ int   g_len[NMAX];
__device__ unsigned long long g_pack[NMAX];
__device__ int   g_perm[NMAX];

// packed f32x2 FFMA: acc(pair) += (a,a) * bp(pair)
#define FFMA2(acc, a, bp)                                                     \
    asm("{\n\t.reg .b64 t;\n\tmov.b64 t, {%1,%1};\n\t"                        \
        "fma.rn.f32x2 %0, t, %2, %0;\n\t}"                                    \
        : "+l"(acc) : "f"(a), "l"(bp))

__device__ __forceinline__ float f2lo(unsigned long long v) {
    return __uint_as_float((unsigned)(v & 0xffffffffull));
}
__device__ __forceinline__ float f2hi(unsigned long long v) {
    return __uint_as_float((unsigned)(v >> 32));
}

// ---- 64x64 mm core: acc[i] (f32x2 pair) = sum_j AT[j][r0+i] * B[j][c0..c0+1]
// 512 thr, 16 warps; warp tile 16x16, lane tile 4 rows x 2 cols.
// Per warp-iter: 1 broadcast LDS.128 (A) + 1 LDS.64 (B) + 4 FFMA2.
__device__ __forceinline__ void mm_acc(const float* __restrict__ AT,
                                       const float* __restrict__ B,
                                       unsigned long long acc[4],
                                       int r0, int c0) {
    const float* ap = AT + r0;
    const float* bp = B + c0;
    acc[0] = acc[1] = acc[2] = acc[3] = 0ull;
#pragma unroll 8
    for (int j = 0; j < 64; j++) {
        float4 x = *(const float4*)(ap + j * SH);
        unsigned long long b2 = *(const unsigned long long*)(bp + j * SH);
        FFMA2(acc[0], x.x, b2); FFMA2(acc[1], x.y, b2);
        FFMA2(acc[2], x.z, b2); FFMA2(acc[3], x.w, b2);
    }
}

__device__ __forceinline__ void store4(float* __restrict__ C,
                                       const unsigned long long acc[4],
                                       int r0, int c0) {
#pragma unroll
    for (int i = 0; i < 4; i++)
        *(unsigned long long*)(C + (r0 + i) * SH + c0) = acc[i];
}

// ---------------- prepare: B_h^k = expm(k*H_h), deg-12 PS, 5 matmuls -----
// blocks 0..79: h = b/10, k = b%10+1 ; block 80: sos ; block 81: grouping
__global__ void __launch_bounds__(512, 1)
prepare_kernel(const float* __restrict__ raw, const int* __restrict__ pw,
               int L, int N) {
    extern __shared__ float sm[];
    int b = blockIdx.x;
    int tid = threadIdx.x;

    if (b == 81) {   // ---- grouping ----
        int* cnt = (int*)sm;
        int* off = cnt + 32;
        if (tid < 20) cnt[tid] = 0;
        __syncthreads();
        for (int n = tid; n < N; n += 512) {
            const int* p = pw + (size_t)n * L;
            int c = 0, len = 0;
            unsigned long long pack = 0ull;
            for (int t = 0; t < L; t++) {
                int wv = p[t];
                int code = (wv == -1) ? 0 : wv;
                pack |= ((unsigned long long)(code & 3)) << (2 * t);
                if (wv != 3) len++;          // PAD = 3
                if (wv == 1) c++;            // only step==1 hits the gate
            }
            int key = (p[0] == -1) ? 100 : c;
            g_key[n] = key; g_len[n] = len; g_pack[n] = pack;
            atomicAdd(&cnt[(key == 100) ? 16 : key], 1);
        }
        __syncthreads();
        if (tid == 0) { int s0 = 0; for (int q = 0; q < 20; q++) { off[q] = s0; s0 += cnt[q]; } }
        __syncthreads();
        for (int n = tid; n < N; n += 512) {
            int key = g_key[n];
            int pos = atomicAdd(&off[(key == 100) ? 16 : key], 1);
            g_perm[pos] = n;
        }
        return;
    }

    int h, kk;
    const float* A;
    if (b == 80) { h = -1; kk = 1; A = raw + (size_t)16 * 4096; }
    else         { h = b / 10; kk = b % 10 + 1; A = raw + (size_t)(8 + h) * 4096; }

    float* M  = sm + 0 * SZ;
    float* MT = sm + 1 * SZ;     // dead after mm2; reused as W2
    float* P2 = sm + 2 * SZ;
    float* P3 = sm + 3 * SZ;
    float* P4 = sm + 4 * SZ;
    float* W1 = sm + 5 * SZ;
    float* W2 = MT;

    int w = tid >> 5, l = tid & 31;
    int wr = w >> 2, wc = w & 3;
    int lr = l >> 3, lc = l & 7;
    int r0 = wr * 16 + lr * 4;
    int c0 = wc * 16 + lc * 2;

    // M = k*(A - A^T)/64 ; MT = -M (skew)
    float scale = (float)kk * (1.0f / 64.0f);
    for (int i = tid; i < 4096; i += 512) {
        int rr = i >> 6, cc = i & 63;
        float v = (A[rr * 64 + cc] - A[cc * 64 + rr]) * scale;
        M[rr * SH + cc]  = v;
        MT[cc * SH + rr] = v;
    }
    __syncthreads();

    unsigned long long acc[4];

    mm_acc(MT, M, acc, r0, c0);                 // P2 = M^2 (symmetric)
    store4(P2, acc, r0, c0);
    __syncthreads();

    mm_acc(MT, P2, acc, r0, c0);                // P3 = M^3
    store4(P3, acc, r0, c0);                    // own cells; no sync needed before P4 mm
    mm_acc(P2, P2, acc, r0, c0);                // P4 = M^4 (symmetric)
    // fused: P4 store + W1 = B2' = I/8! + M/9! + P2/10! + P3/11! + P4/12!
#pragma unroll
    for (int i = 0; i < 4; i++) {
        int r = r0 + i;
        float p4x = f2lo(acc[i]), p4y = f2hi(acc[i]);
        *(unsigned long long*)(P4 + r * SH + c0) = acc[i];
        float2 mv  = *(const float2*)(M  + r * SH + c0);
        float2 p2v = *(const float2*)(P2 + r * SH + c0);
        float2 p3v = *(const float2*)(P3 + r * SH + c0);
        float d0 = (r == c0)     ? 1.f : 0.f;
        float d1 = (r == c0 + 1) ? 1.f : 0.f;
        float2 wv;
        wv.x = 2.48015873e-5f * d0 + 2.75573192e-6f * mv.x
             + 2.75573192e-7f * p2v.x + 2.50521084e-8f * p3v.x
             + 2.08767570e-9f * p4x;
        wv.y = 2.48015873e-5f * d1 + 2.75573192e-6f * mv.y
             + 2.75573192e-7f * p2v.y + 2.50521084e-8f * p3v.y
             + 2.08767570e-9f * p4y;
        *(float2*)(W1 + r * SH + c0) = wv;
    }
    __syncthreads();

    mm_acc(P4, W1, acc, r0, c0);                // W2 = P4*B2' + B1
#pragma unroll
    for (int i = 0; i < 4; i++) {
        int r = r0 + i;
        float2 mv  = *(const float2*)(M  + r * SH + c0);
        float2 p2v = *(const float2*)(P2 + r * SH + c0);
        float2 p3v = *(const float2*)(P3 + r * SH + c0);
        float d0 = (r == c0)     ? 1.f : 0.f;
        float d1 = (r == c0 + 1) ? 1.f : 0.f;
        float2 wv;
        wv.x = f2lo(acc[i]) + (1.f / 24.f) * d0 + (1.f / 120.f) * mv.x
             + 1.38888889e-3f * p2v.x + 1.98412698e-4f * p3v.x;
        wv.y = f2hi(acc[i]) + (1.f / 24.f) * d1 + (1.f / 120.f) * mv.y
             + 1.38888889e-3f * p2v.y + 1.98412698e-4f * p3v.y;
        *(float2*)(W2 + r * SH + c0) = wv;
    }
    __syncthreads();

    mm_acc(P4, W2, acc, r0, c0);                // E = P4*W2 + B0
    float* dst = (h < 0) ? g_sos : g_powers[h][kk];
#pragma unroll
    for (int i = 0; i < 4; i++) {
        int r = r0 + i;
        float2 mv  = *(const float2*)(M  + r * SH + c0);
        float2 p2v = *(const float2*)(P2 + r * SH + c0);
        float2 p3v = *(const float2*)(P3 + r * SH + c0);
        float d0 = (r == c0)     ? 1.f : 0.f;
        float d1 = (r == c0 + 1) ? 1.f : 0.f;
        float ex = f2lo(acc[i]) + d0 + mv.x + 0.5f * p2v.x + (1.f / 6.f) * p3v.x;
        float ey = f2hi(acc[i]) + d1 + mv.y + 0.5f * p2v.y + (1.f / 6.f) * p3v.y;
        float2 ev = make_float2(ex, ey);
        *(float2*)(dst + r * 64 + c0) = ev;
        if (h >= 0 && kk == 1)    // also publish identity as power 0
            *(float2*)(g_powers[h][0] + r * 64 + c0) = make_float2(d0, d1);
    }
}

// ---------------- fused output: maps (256 MB) + steps (16 MB) ------------
__global__ void __launch_bounds__(256)
output_kernel(float4* __restrict__ out, float* __restrict__ steps_out, int N) {
    int b = blockIdx.x;
    int t = threadIdx.x;
    if (b < 2048) {              // ---- maps gather-broadcast ----
        int h = b & 7;
        int base = (b >> 3) << 3;
        float4 v0, v1, v2, v3;
        int cached = -12345;
#pragma unroll 1
        for (int e = 0; e < 8; e++) {
            int n = g_perm[base + e];
            int key = g_key[n];
            if (key != cached) {
                const float4* src = (key == 100) ? (const float4*)g_sos
                                                 : (const float4*)g_powers[h][key];
                v0 = src[t]; v1 = src[t + 256]; v2 = src[t + 512]; v3 = src[t + 768];
                cached = key;
            }
            float4* dst = out + ((size_t)((unsigned)(n * NHEADS + h)) << 10);
            __stcs(dst + t,       v0);
            __stcs(dst + t + 256, v1);
            __stcs(dst + t + 512, v2);
            __stcs(dst + t + 768, v3);
        }
    } else {                     // ---- steps row ----
        int i = b - 2048;
        unsigned long long pi = g_pack[i];
        int li = g_len[i];
        int j0 = t << 3;
        float v[8];
#pragma unroll
        for (int q = 0; q < 8; q++) {
            int j = j0 + q;
            unsigned long long d = pi ^ g_pack[j];
            int lj = g_len[j];
            int pos = d ? ((__ffsll((long long)d) - 1) >> 1) : 64;
            int mn = min(li, lj), mx = max(li, lj);
            v[q] = (float)(mx - min(pos, mn));
        }
        float4* row = (float4*)(steps_out + (size_t)i * N + j0);
        __stcs(row,     make_float4(v[0], v[1], v[2], v[3]));
        __stcs(row + 1, make_float4(v[4], v[5], v[6], v[7]));
    }
}

// ---------------- launch --------------------------------------------------
extern "C" void kernel_launch(void* const* d_in, const int* in_sizes, int n_in,
                              void* d_out, int out_size) {
    const float* raw = (const float*)d_in[0];
    const int*   pw  = (const int*)d_in[1];
    const int N = 2048;
    const int L = in_sizes[1] / N;
    float* out = (float*)d_out;

    size_t smem = 6ull * SZ * sizeof(float);   // ~104 KB
    cudaFuncSetAttribute(prepare_kernel, cudaFuncAttributeMaxDynamicSharedMemorySize,
                         (int)smem);

    prepare_kernel<<<82, 512, smem>>>(raw, pw, L, N);

    size_t maps_elems = (size_t)N * NHEADS * 64 * 64;
    bool has_steps = (size_t)out_size >= maps_elems + (size_t)N * N;
    int grid = has_steps ? 4096 : 2048;
    output_kernel<<<grid, 256>>>((float4*)out, out + maps_elems, N);
}